// round 9
// baseline (speedup 1.0000x reference)
#include <cuda_runtime.h>

// 8192x8192 fp32 input; 10 3x3 SAME convs; 4 2x2 maxpools.
// Stages: [conv,conv,pool] x2 then [conv,conv,conv,pool] x2.
// R9 = R8 structure + f32x2 packed-FMA interior conv (2 px per FFMA2).

__device__ float g_buf0[4096u * 4096u];
__device__ float g_buf1[2048u * 2048u];
__device__ float g_buf2[1024u * 1024u];

#define NT 320                 // threads per block (10 warps)
#define BD 72                  // smem buffer dim (stride), 16B-aligned rows
#define STRIPS 17              // 17 x 17 threads x (4x4 px) cover 68x68
#define NACT (STRIPS * STRIPS) // 289 active conv threads

// ---- packed fp32x2 primitives ----
__device__ __forceinline__ float2 pack2(float x, float y) {
    float2 r;
    asm("mov.b64 %0, {%1, %2};"
        : "=l"(*(unsigned long long*)&r) : "f"(x), "f"(y));
    return r;
}
__device__ __forceinline__ float2 ffma2(float2 a, float2 b, float2 c) {
    float2 d;
    asm("fma.rn.f32x2 %0, %1, %2, %3;"
        : "=l"(*(unsigned long long*)&d)
        : "l"(*(unsigned long long*)&a),
          "l"(*(unsigned long long*)&b),
          "l"(*(unsigned long long*)&c));
    return d;
}
__device__ __forceinline__ float2 fmul2(float2 a, float2 b) {
    float2 d;
    asm("mul.rn.f32x2 %0, %1, %2;"
        : "=l"(*(unsigned long long*)&d)
        : "l"(*(unsigned long long*)&a),
          "l"(*(unsigned long long*)&b));
    return d;
}

// One source row as operand pairs for two output pairs.
// Window cols (rel): a0=(0,1) a1=(2,3) b0=(4,5) natural pairs;
// c0=(1,2) c1=(3,4) crossing pairs (2 packs).
struct Row {
    float2 a0, a1, b0, c0, c1;
};

__device__ __forceinline__ Row load_row(const float* sp) {
    Row r;
    float4 A = *(const float4*)sp;        // cols 0..3 (16B aligned)
    float2 B = *(const float2*)(sp + 4);  // cols 4..5 (8B aligned)
    r.a0 = make_float2(A.x, A.y);
    r.a1 = make_float2(A.z, A.w);
    r.b0 = B;
    r.c0 = pack2(A.y, A.z);
    r.c1 = pack2(A.w, B.x);
    return r;
}

// Two output pairs (cols 0..3 rel) from 3 source rows. Tap order matches the
// scalar version (left-to-right, top-to-bottom) for identical rounding.
__device__ __forceinline__ void conv2(float2& O0, float2& O1,
                                      const Row& r0, const Row& r1,
                                      const Row& r2, const float2 k[9]) {
    O0 = fmul2(r0.a0, k[0]);
    O0 = ffma2(r0.c0, k[1], O0);
    O0 = ffma2(r0.a1, k[2], O0);
    O0 = ffma2(r1.a0, k[3], O0);
    O0 = ffma2(r1.c0, k[4], O0);
    O0 = ffma2(r1.a1, k[5], O0);
    O0 = ffma2(r2.a0, k[6], O0);
    O0 = ffma2(r2.c0, k[7], O0);
    O0 = ffma2(r2.a1, k[8], O0);

    O1 = fmul2(r0.a1, k[0]);
    O1 = ffma2(r0.c1, k[1], O1);
    O1 = ffma2(r0.b0, k[2], O1);
    O1 = ffma2(r1.a1, k[3], O1);
    O1 = ffma2(r1.c1, k[4], O1);
    O1 = ffma2(r1.b0, k[5], O1);
    O1 = ffma2(r2.a1, k[6], O1);
    O1 = ffma2(r2.c1, k[7], O1);
    O1 = ffma2(r2.b0, k[8], O1);
}

// Interior mid conv layer (f32x2), shifted-origin:
// dst[r][x] = conv(src)[r+1][x+1]; thread covers dst cols 4s..4s+3, rows 4g..4g+3.
__device__ __forceinline__ void layer_mid_v2(const float* __restrict__ src,
                                             float* __restrict__ dst,
                                             const float2 k[9], int s, int g) {
    const float* sp = src + (4 * g) * BD + 4 * s;
    Row r[3];
    r[0] = load_row(sp);
    r[1] = load_row(sp + BD);
#pragma unroll
    for (int j = 0; j < 4; ++j) {
        r[(j + 2) % 3] = load_row(sp + (2 + j) * BD);
        float2 O0, O1;
        conv2(O0, O1, r[j % 3], r[(j + 1) % 3], r[(j + 2) % 3], k);
        float* dp = dst + (4 * g + j) * BD + 4 * s;
        *(float2*)dp = O0;
        *(float2*)(dp + 2) = O1;
    }
}

// Interior last conv layer fused with 2x2 maxpool (f32x2); s,g < 16.
__device__ __forceinline__ void layer_pool_v2(const float* __restrict__ src,
                                              float* __restrict__ out, int outW,
                                              const float2 k[9], int s, int g,
                                              int oy, int ox) {
    const float* sp = src + (4 * g) * BD + 4 * s;
    Row r[3];
    r[0] = load_row(sp);
    r[1] = load_row(sp + BD);
    float m0, m1;
#pragma unroll
    for (int j = 0; j < 4; ++j) {
        r[(j + 2) % 3] = load_row(sp + (2 + j) * BD);
        float2 O0, O1;
        conv2(O0, O1, r[j % 3], r[(j + 1) % 3], r[(j + 2) % 3], k);
        float a = fmaxf(O0.x, O0.y);
        float b = fmaxf(O1.x, O1.y);
        if ((j & 1) == 0) { m0 = a; m1 = b; }
        else {
            float* op = out + (long)(oy + 2 * g + (j >> 1)) * outW + ox + 2 * s;
            *(float2*)op = make_float2(fmaxf(m0, a), fmaxf(m1, b));
        }
    }
}

// ---- scalar masked path for edge blocks (proven R8 code) ----
__device__ __forceinline__ void ld8(float* d, const float* p) {
    float4 a = *(const float4*)(p);
    float4 b = *(const float4*)(p + 4);
    d[0] = a.x; d[1] = a.y; d[2] = a.z; d[3] = a.w;
    d[4] = b.x; d[5] = b.y; d[6] = b.z; d[7] = b.w;
}

__device__ __forceinline__ void conv_row(float v[4], const float* r0,
                                         const float* r1, const float* r2,
                                         const float k[9]) {
#pragma unroll
    for (int q = 0; q < 4; ++q) {
        v[q] = r0[q] * k[0] + r0[q + 1] * k[1] + r0[q + 2] * k[2]
             + r1[q] * k[3] + r1[q + 1] * k[4] + r1[q + 2] * k[5]
             + r2[q] * k[6] + r2[q + 1] * k[7] + r2[q + 2] * k[8];
    }
}

__device__ __forceinline__ void layer_mid_edge(const float* __restrict__ src,
                                               float* __restrict__ dst,
                                               const float k[9], int s, int g,
                                               int ey0, int ex0, unsigned uw) {
    const float* sp = src + (4 * g) * BD + 4 * s;
    float r[3][8];
    ld8(r[0], sp);
    ld8(r[1], sp + BD);
#pragma unroll
    for (int j = 0; j < 4; ++j) {
        ld8(r[(j + 2) % 3], sp + (2 + j) * BD);
        float v[4];
        conv_row(v, r[j % 3], r[(j + 1) % 3], r[(j + 2) % 3], k);
        const bool rok = (unsigned)(ey0 + 4 * g + j) < uw;  // SAME at image edge
#pragma unroll
        for (int q = 0; q < 4; ++q)
            if (!(rok && ((unsigned)(ex0 + 4 * s + q) < uw))) v[q] = 0.0f;
        *(float4*)(dst + (4 * g + j) * BD + 4 * s) =
            make_float4(v[0], v[1], v[2], v[3]);
    }
}

// Fused stage: K 3x3 convs (SAME at image boundary) + 2x2 maxpool.
// Block -> 32x32 pooled tile (64x64 pre-pool). EXT = 64 + 2K loaded extent.
template <int K>
__global__ __launch_bounds__(NT, 3)
void stage_kernel(const float* __restrict__ in, int inW,
                  float* __restrict__ out, int outW,
                  const float* __restrict__ w0,
                  const float* __restrict__ w1,
                  const float* __restrict__ w2) {
    constexpr int EXT = 64 + 2 * K;
    __shared__ float bufA[BD * BD];
    __shared__ float bufB[BD * BD];
    __shared__ float wts[27];

    const int tid = threadIdx.x;
    if (tid < K * 9) {
        const float* wp = (tid < 9) ? w0 : ((tid < 18) ? w1 : w2);
        wts[tid] = wp[tid % 9];
    }

    const int gx0 = blockIdx.x * 64 - K;
    const int gy0 = blockIdx.y * 64 - K;
    const unsigned uw = (unsigned)inW;  // square image
    const bool edge = (gx0 < 0) || (gy0 < 0) ||
                      (gx0 + EXT > inW) || (gy0 + EXT > inW);

    if (!edge) {
        // Interior: no zero-init needed (junk cells never reach the pooled
        // output; finite values only). K=2: full unconditional window load.
        if (K == 2) {
            if (tid < 288) {
                const int tc = tid % 36;            // float2 column
                const int tr = tid / 36;            // 8 concurrent rows
                const float* gp = in + (long)(gy0 + tr) * inW + gx0 + 2 * tc;
                float* bp = bufA + tr * BD + 2 * tc;
#pragma unroll
                for (int r = 0; r < 9; ++r, gp += 8L * inW, bp += 8 * BD)
                    *(float2*)bp = *(const float2*)gp;
            }
        } else {
            for (int i = tid; i < BD * BD; i += NT) {
                int r = i / BD, c = i - r * BD;
                if (r < EXT && c < EXT)
                    bufA[i] = in[(long)(gy0 + r) * inW + (gx0 + c)];
            }
        }
    } else {
        for (int i = tid; i < BD * BD; i += NT) {
            int r = i / BD, c = i - r * BD;
            float v = 0.0f;
            if (r < EXT && c < EXT) {
                int gy = gy0 + r, gx = gx0 + c;
                if ((unsigned)gy < uw && (unsigned)gx < uw)
                    v = in[(long)gy * inW + gx];
            }
            bufA[i] = v;
            bufB[i] = 0.0f;
        }
    }
    __syncthreads();

    const bool active = tid < NACT;
    const int s = tid % STRIPS;
    const int g = tid / STRIPS;
    const int ox = blockIdx.x * 32, oy = blockIdx.y * 32;

    float* src = bufA;
    float* dst = bufB;

    if (!edge) {
        // ---- interior: f32x2 path ----
        float2 k2[9];
#pragma unroll
        for (int c = 0; c < K - 1; ++c) {
            if (active) {
#pragma unroll
                for (int m = 0; m < 9; ++m) {
                    float kv = wts[c * 9 + m];
                    k2[m] = pack2(kv, kv);
                }
                layer_mid_v2(src, dst, k2, s, g);
            }
            __syncthreads();
            float* t = src; src = dst; dst = t;
        }
        if (active && s < 16 && g < 16) {
#pragma unroll
            for (int m = 0; m < 9; ++m) {
                float kv = wts[(K - 1) * 9 + m];
                k2[m] = pack2(kv, kv);
            }
            layer_pool_v2(src, out, outW, k2, s, g, oy, ox);
        }
        // no further smem use; no sync needed before exit
    } else {
        // ---- edge: scalar masked path ----
        float k[9];
#pragma unroll
        for (int c = 0; c < K; ++c) {
            if (active) {
#pragma unroll
                for (int m = 0; m < 9; ++m) k[m] = wts[c * 9 + m];
                layer_mid_edge(src, dst, k, s, g,
                               gy0 + c + 1, gx0 + c + 1, uw);
            }
            __syncthreads();
            float* t = src; src = dst; dst = t;
        }
        // Pool over src [0,64)^2 (buf coord 0 == abs blockIdx*64).
        for (int i = tid; i < 1024; i += NT) {
            int py = i >> 5, px = i & 31;
            const float* p = src + (2 * py) * BD + 2 * px;
            float m = fmaxf(fmaxf(p[0], p[1]), fmaxf(p[BD], p[BD + 1]));
            out[(long)(oy + py) * outW + ox + px] = m;
        }
    }
}

extern "C" void kernel_launch(void* const* d_in, const int* in_sizes, int n_in,
                              void* d_out, int out_size) {
    const float* x = (const float*)d_in[0];
    const float* w[10];
    for (int i = 0; i < 10; ++i) w[i] = (const float*)d_in[1 + i];

    float *b0, *b1, *b2;
    cudaGetSymbolAddress((void**)&b0, g_buf0);
    cudaGetSymbolAddress((void**)&b1, g_buf1);
    cudaGetSymbolAddress((void**)&b2, g_buf2);

    float* outp = (float*)d_out;

    stage_kernel<2><<<dim3(128, 128), NT>>>(x,  8192, b0,  4096, w[0], w[1], nullptr);
    stage_kernel<2><<<dim3(64, 64),   NT>>>(b0, 4096, b1,  2048, w[2], w[3], nullptr);
    stage_kernel<3><<<dim3(32, 32),   NT>>>(b1, 2048, b2,  1024, w[4], w[5], w[6]);
    stage_kernel<3><<<dim3(16, 16),   NT>>>(b2, 1024, outp, 512, w[7], w[8], w[9]);
}